// round 4
// baseline (speedup 1.0000x reference)
#include <cuda_runtime.h>

#define BB 32
#define NN 4096
#define DD 256
#define HH 8
#define TT 28
#define ROWS (BB * NN)
#define BLK 128

typedef unsigned long long u64;

// ---------- packed f32x2 ops on opaque u64 register pairs ----------
__device__ __forceinline__ u64 ffma2(u64 a, u64 b, u64 c) {
    u64 d; asm("fma.rn.f32x2 %0, %1, %2, %3;" : "=l"(d) : "l"(a), "l"(b), "l"(c)); return d;
}
__device__ __forceinline__ u64 pk(float lo, float hi) {
    u64 r; asm("mov.b64 %0, {%1,%2};" : "=l"(r) : "f"(lo), "f"(hi)); return r;
}
__device__ __forceinline__ float2 upk(u64 v) {
    float2 f; asm("mov.b64 {%0,%1}, %2;" : "=f"(f.x), "=f"(f.y) : "l"(v)); return f;
}
__device__ __forceinline__ u64 dup2(float v) { return pk(v, v); }

__device__ __forceinline__ float fex2(float x) {
    float y; asm("ex2.approx.f32 %0, %1;" : "=f"(y) : "f"(x)); return y;
}
__device__ __forceinline__ float frcp(float x) {
    float y; asm("rcp.approx.f32 %0, %1;" : "=f"(y) : "f"(x)); return y;
}

#define L2E 1.4426950408889634f
#define NEG1U 0xBF800000BF800000ULL  // (-1.0f, -1.0f)

// sigmoid of both lanes sharing one reciprocal: 2 EX2 + 1 RCP
__device__ __forceinline__ u64 sigmoid2u(u64 v) {
    float2 f = upk(v);
    float ea = fex2(-L2E * f.x);
    float eb = fex2(-L2E * f.y);
    float sa = 1.0f + ea, sb = 1.0f + eb;
    float ip = frcp(sa * sb);
    return pk(sb * ip, sa * ip);
}
// tanh of both lanes via exp(2x), sharing one reciprocal
__device__ __forceinline__ u64 tanh2u(u64 v) {
    float2 f = upk(v);
    float ta = fex2(2.0f * L2E * f.x);
    float tb = fex2(2.0f * L2E * f.y);
    float pa = ta + 1.0f, pb = tb + 1.0f;
    float ip = frcp(pa * pb);
    return pk((ta - 1.0f) * pb * ip, (tb - 1.0f) * pa * ip);
}

struct Smem {
    float4     xs[BLK][8];        // staged x chunk (128 rows x 32 cols), XOR swizzle
    ulonglong2 wproj2[DD][4];     // [d][p] = out pairs (2p,2p+1) of [Wp;Wg1] at col d
    ulonglong2 whh2[HH][6];       // [j][q] = out pairs (2q,2q+1) of W_hh col j
    ulonglong2 wih2[6];           // pairs of w_ih
    ulonglong2 bsum2[4];          // pairs of (b_ih+b_hh)[0..15]  (r,z gates)
    ulonglong2 bihn2[2];          // pairs of b_ih[16..23]
    ulonglong2 bhhn2[2];          // pairs of b_hh[16..23]
    ulonglong2 wg22[TT][2];       // [t] = Wg2 row t as 4 pairs
    u64 wo_p[4];
    u64 bp_p[4];
    u64 bg1_p[4];
    float bg2[TT];
    float dc[TT];
    float bo;
};

__global__ void __launch_bounds__(BLK, 4)
horizon_kernel(const float* __restrict__ x, const float* __restrict__ last_step,
               const float* __restrict__ W_ih, const float* __restrict__ W_hh,
               const float* __restrict__ b_ih, const float* __restrict__ b_hh,
               const float* __restrict__ Wp, const float* __restrict__ bp,
               const float* __restrict__ Wo, const float* __restrict__ bo,
               const float* __restrict__ Wg1, const float* __restrict__ bg1,
               const float* __restrict__ Wg2, const float* __restrict__ bg2,
               const float* __restrict__ log_decay, float* __restrict__ out) {
    __shared__ Smem s;
    const int tid = threadIdx.x;
    const int rb = blockIdx.x * BLK;

    // ---------------- weight prep (packed u64-pair layouts) ----------------
    for (int i = tid; i < DD * 4; i += BLK) {
        int d = i >> 2, p = i & 3;
        float v0, v1, v2, v3;
        if (p < 2) {
            int o = 4 * p;
            v0 = Wp[(o + 0) * DD + d]; v1 = Wp[(o + 1) * DD + d];
            v2 = Wp[(o + 2) * DD + d]; v3 = Wp[(o + 3) * DD + d];
        } else {
            int o = 4 * p - 8;
            v0 = Wg1[(o + 0) * DD + d]; v1 = Wg1[(o + 1) * DD + d];
            v2 = Wg1[(o + 2) * DD + d]; v3 = Wg1[(o + 3) * DD + d];
        }
        s.wproj2[d][p] = make_ulonglong2(pk(v0, v1), pk(v2, v3));
    }
    if (tid < 48) {
        int j = tid / 6, q = tid % 6;
        int k = 4 * q;
        s.whh2[j][q] = make_ulonglong2(
            pk(W_hh[(k + 0) * HH + j], W_hh[(k + 1) * HH + j]),
            pk(W_hh[(k + 2) * HH + j], W_hh[(k + 3) * HH + j]));
    }
    if (tid < 6) {
        int k = 4 * tid;
        s.wih2[tid] = make_ulonglong2(pk(W_ih[k], W_ih[k + 1]), pk(W_ih[k + 2], W_ih[k + 3]));
    }
    if (tid < 4) {
        int k = 4 * tid;
        s.bsum2[tid] = make_ulonglong2(pk(b_ih[k] + b_hh[k], b_ih[k + 1] + b_hh[k + 1]),
                                       pk(b_ih[k + 2] + b_hh[k + 2], b_ih[k + 3] + b_hh[k + 3]));
        s.wo_p[tid]  = pk(Wo[2 * tid], Wo[2 * tid + 1]);
        s.bp_p[tid]  = pk(bp[2 * tid], bp[2 * tid + 1]);
        s.bg1_p[tid] = pk(bg1[2 * tid], bg1[2 * tid + 1]);
    }
    if (tid < 2) {
        int k = 16 + 4 * tid;
        s.bihn2[tid] = make_ulonglong2(pk(b_ih[k], b_ih[k + 1]), pk(b_ih[k + 2], b_ih[k + 3]));
        s.bhhn2[tid] = make_ulonglong2(pk(b_hh[k], b_hh[k + 1]), pk(b_hh[k + 2], b_hh[k + 3]));
    }
    if (tid < 56) {
        int t = tid >> 1, half = tid & 1;
        int k = t * HH + 4 * half;
        s.wg22[t][half] = make_ulonglong2(pk(Wg2[k], Wg2[k + 1]), pk(Wg2[k + 2], Wg2[k + 3]));
    }
    if (tid < TT) {
        s.bg2[tid] = bg2[tid];
        float edc = __expf(log_decay[0]);
        s.dc[tid] = __expf(-edc * (float)(tid + 1));
    }
    if (tid == 0) s.bo = bo[0];
    __syncthreads();

    // ---------------- projections: h0 (Wp) and g1pre (Wg1) ----------------
    u64 acc[8];
#pragma unroll
    for (int p = 0; p < 4; p++) acc[p] = s.bp_p[p];
#pragma unroll
    for (int p = 0; p < 4; p++) acc[4 + p] = s.bg1_p[p];

#pragma unroll 1
    for (int c = 0; c < 8; c++) {
        __syncthreads();
#pragma unroll
        for (int k = 0; k < 8; k++) {
            int idx = k * BLK + tid;
            int r = idx >> 3, q = idx & 7;
            float4 v = ((const float4*)(x + (size_t)(rb + r) * DD + c * 32))[q];
            s.xs[r][q ^ (r & 7)] = v;
        }
        __syncthreads();
#pragma unroll
        for (int q = 0; q < 8; q++) {
            float4 xv = s.xs[tid][q ^ (tid & 7)];
            float xe0 = xv.x, xe1 = xv.y, xe2 = xv.z, xe3 = xv.w;
            int dbase = (c << 5) + (q << 2);
#pragma unroll
            for (int e = 0; e < 4; e++) {
                float xs_e = (e == 0) ? xe0 : (e == 1) ? xe1 : (e == 2) ? xe2 : xe3;
                u64 xd = dup2(xs_e);
                ulonglong2 w01 = s.wproj2[dbase + e][0];
                ulonglong2 w23 = s.wproj2[dbase + e][1];
                ulonglong2 w45 = s.wproj2[dbase + e][2];
                ulonglong2 w67 = s.wproj2[dbase + e][3];
                acc[0] = ffma2(w01.x, xd, acc[0]);
                acc[1] = ffma2(w01.y, xd, acc[1]);
                acc[2] = ffma2(w23.x, xd, acc[2]);
                acc[3] = ffma2(w23.y, xd, acc[3]);
                acc[4] = ffma2(w45.x, xd, acc[4]);
                acc[5] = ffma2(w45.y, xd, acc[5]);
                acc[6] = ffma2(w67.x, xd, acc[6]);
                acc[7] = ffma2(w67.y, xd, acc[7]);
            }
        }
    }

    u64 h[4];
#pragma unroll
    for (int p = 0; p < 4; p++) h[p] = acc[p];
    u64 g1u[4];
#pragma unroll
    for (int p = 0; p < 4; p++) {
        float2 f = upk(acc[4 + p]);
        g1u[p] = pk(fmaxf(f.x, 0.0f), fmaxf(f.y, 0.0f));
    }

    // unpacked h lanes for broadcast
    float hs[8];
#pragma unroll
    for (int p = 0; p < 4; p++) {
        float2 f = upk(h[p]);
        hs[2 * p] = f.x; hs[2 * p + 1] = f.y;
    }

    // ---------------- GRU rollout fused with gate + decay + output ----------------
    float last = last_step[rb + tid];
    float cur = last;
    float* outrow = out + (size_t)(rb + tid) * TT;

#pragma unroll 1
    for (int t = 0; t < TT; t++) {
        // a[k] accumulates (gi+gh) for output pair (2k,2k+1), k=0..7 (r,z gates)
        u64 a[8];
#pragma unroll
        for (int qq = 0; qq < 4; qq++) {
            ulonglong2 b = s.bsum2[qq];
            a[2 * qq] = b.x; a[2 * qq + 1] = b.y;
        }
        u64 ain[4], ahn[4];
        {
            ulonglong2 bi0 = s.bihn2[0], bi1 = s.bihn2[1];
            ain[0] = bi0.x; ain[1] = bi0.y; ain[2] = bi1.x; ain[3] = bi1.y;
            ulonglong2 bh0 = s.bhhn2[0], bh1 = s.bhhn2[1];
            ahn[0] = bh0.x; ahn[1] = bh0.y; ahn[2] = bh1.x; ahn[3] = bh1.y;
        }
        // gi contribution: cur * w_ih
        u64 curd = dup2(cur);
#pragma unroll
        for (int q = 0; q < 4; q++) {
            ulonglong2 w = s.wih2[q];
            a[2 * q]     = ffma2(w.x, curd, a[2 * q]);
            a[2 * q + 1] = ffma2(w.y, curd, a[2 * q + 1]);
        }
#pragma unroll
        for (int q = 4; q < 6; q++) {
            ulonglong2 w = s.wih2[q];
            ain[2 * (q - 4)]     = ffma2(w.x, curd, ain[2 * (q - 4)]);
            ain[2 * (q - 4) + 1] = ffma2(w.y, curd, ain[2 * (q - 4) + 1]);
        }
        // gh contribution: h @ W_hh^T
#pragma unroll
        for (int j = 0; j < 8; j++) {
            u64 hd = dup2(hs[j]);
            ulonglong2 w0 = s.whh2[j][0];
            ulonglong2 w1 = s.whh2[j][1];
            ulonglong2 w2 = s.whh2[j][2];
            ulonglong2 w3 = s.whh2[j][3];
            ulonglong2 w4 = s.whh2[j][4];
            ulonglong2 w5 = s.whh2[j][5];
            a[0] = ffma2(w0.x, hd, a[0]);
            a[1] = ffma2(w0.y, hd, a[1]);
            a[2] = ffma2(w1.x, hd, a[2]);
            a[3] = ffma2(w1.y, hd, a[3]);
            a[4] = ffma2(w2.x, hd, a[4]);
            a[5] = ffma2(w2.y, hd, a[5]);
            a[6] = ffma2(w3.x, hd, a[6]);
            a[7] = ffma2(w3.y, hd, a[7]);
            ahn[0] = ffma2(w4.x, hd, ahn[0]);
            ahn[1] = ffma2(w4.y, hd, ahn[1]);
            ahn[2] = ffma2(w5.x, hd, ahn[2]);
            ahn[3] = ffma2(w5.y, hd, ahn[3]);
        }
        // gates
        u64 pacc = 0ULL;
#pragma unroll
        for (int p = 0; p < 4; p++) {
            u64 r = sigmoid2u(a[p]);
            u64 z = sigmoid2u(a[4 + p]);
            u64 n = tanh2u(ffma2(r, ahn[p], ain[p]));
            u64 dmn = ffma2(n, NEG1U, h[p]);     // h - n
            u64 hn = ffma2(z, dmn, n);           // n + z*(h-n)
            h[p] = hn;
            float2 hf = upk(hn);
            hs[2 * p] = hf.x; hs[2 * p + 1] = hf.y;
            pacc = ffma2(hn, s.wo_p[p], pacc);
        }
        float2 pf = upk(pacc);
        float pred = pf.x + pf.y + s.bo;
        cur = pred;

        // gate_t = sigmoid(g1 . Wg2[t] + bg2[t])
        ulonglong2 wg0 = s.wg22[t][0], wg1v = s.wg22[t][1];
        u64 lacc = ffma2(g1u[0], wg0.x, pk(s.bg2[t], 0.0f));
        lacc = ffma2(g1u[1], wg0.y, lacc);
        lacc = ffma2(g1u[2], wg1v.x, lacc);
        lacc = ffma2(g1u[3], wg1v.y, lacc);
        float2 lf = upk(lacc);
        float lg = lf.x + lf.y;
        float gate = frcp(1.0f + fex2(-L2E * lg));

        float gd = last * s.dc[t];
        float f = fmaf(gate, pred - gd, gd);   // gate*pred + (1-gate)*gd
        outrow[t] = f;
    }
}

extern "C" void kernel_launch(void* const* d_in, const int* in_sizes, int n_in,
                              void* d_out, int out_size) {
    const float* x         = (const float*)d_in[0];
    const float* last_step = (const float*)d_in[1];
    const float* W_ih      = (const float*)d_in[2];
    const float* W_hh      = (const float*)d_in[3];
    const float* b_ih      = (const float*)d_in[4];
    const float* b_hh      = (const float*)d_in[5];
    const float* Wp        = (const float*)d_in[6];
    const float* bp        = (const float*)d_in[7];
    const float* Wo        = (const float*)d_in[8];
    const float* bo        = (const float*)d_in[9];
    const float* Wg1       = (const float*)d_in[10];
    const float* bg1       = (const float*)d_in[11];
    const float* Wg2       = (const float*)d_in[12];
    const float* bg2       = (const float*)d_in[13];
    const float* log_decay = (const float*)d_in[14];
    float* out = (float*)d_out;

    horizon_kernel<<<ROWS / BLK, BLK>>>(x, last_step, W_ih, W_hh, b_ih, b_hh,
                                        Wp, bp, Wo, bo, Wg1, bg1, Wg2, bg2,
                                        log_decay, out);
}

// round 5
// speedup vs baseline: 1.6393x; 1.6393x over previous
#include <cuda_runtime.h>

#define BB 32
#define NN 4096
#define DD 256
#define HH 8
#define TT 28
#define ROWS (BB * NN)
#define BLK 128
#define RPB 64              // rows per block (2 threads per row)

typedef unsigned long long u64;

// ---------- packed f32x2 ops on opaque u64 register pairs ----------
__device__ __forceinline__ u64 ffma2(u64 a, u64 b, u64 c) {
    u64 d; asm("fma.rn.f32x2 %0, %1, %2, %3;" : "=l"(d) : "l"(a), "l"(b), "l"(c)); return d;
}
__device__ __forceinline__ u64 pk(float lo, float hi) {
    u64 r; asm("mov.b64 %0, {%1,%2};" : "=l"(r) : "f"(lo), "f"(hi)); return r;
}
__device__ __forceinline__ float2 upk(u64 v) {
    float2 f; asm("mov.b64 {%0,%1}, %2;" : "=f"(f.x), "=f"(f.y) : "l"(v)); return f;
}
__device__ __forceinline__ u64 dup2(float v) { return pk(v, v); }

__device__ __forceinline__ float fex2(float x) {
    float y; asm("ex2.approx.f32 %0, %1;" : "=f"(y) : "f"(x)); return y;
}
__device__ __forceinline__ float frcp(float x) {
    float y; asm("rcp.approx.f32 %0, %1;" : "=f"(y) : "f"(x)); return y;
}

#define L2E 1.4426950408889634f
#define NEG1U 0xBF800000BF800000ULL  // (-1.0f, -1.0f)

// sigmoid of both lanes sharing one reciprocal: 2 EX2 + 1 RCP
__device__ __forceinline__ u64 sigmoid2u(u64 v) {
    float2 f = upk(v);
    float ea = fex2(-L2E * f.x);
    float eb = fex2(-L2E * f.y);
    float sa = 1.0f + ea, sb = 1.0f + eb;
    float ip = frcp(sa * sb);
    return pk(sb * ip, sa * ip);
}
// tanh of both lanes via exp(2x), sharing one reciprocal
__device__ __forceinline__ u64 tanh2u(u64 v) {
    float2 f = upk(v);
    float ta = fex2(2.0f * L2E * f.x);
    float tb = fex2(2.0f * L2E * f.y);
    float pa = ta + 1.0f, pb = tb + 1.0f;
    float ip = frcp(pa * pb);
    return pk((ta - 1.0f) * pb * ip, (tb - 1.0f) * pa * ip);
}

struct Smem {
    float4     xs[RPB][8];          // staged x chunk (64 rows x 32 cols), XOR swizzle (8KB)
    ulonglong2 wprojs[DD][2][2];    // [d][sub][g]: g=0 Wp pairs(2s,2s+1), g=1 Wg1 (16KB)
    ulonglong2 whhs[HH][2][3];      // [j][sub][gate r/z/n]: W_hh pairs for sub's 4 lanes
    ulonglong2 wihs[2][3];          // [sub][gate]: w_ih pairs
    ulonglong2 bsums[2][2];         // [sub][0]=r (b_ih+b_hh) pairs, [1]=z pairs
    ulonglong2 bains[2];            // [sub]: b_ih n-gate pairs
    ulonglong2 bahns[2];            // [sub]: b_hh n-gate pairs
    ulonglong2 wg2s[TT][2];         // [t][sub]: Wg2 row t pairs(2s,2s+1)
    ulonglong2 wos[2];              // [sub]: Wo pairs
    ulonglong2 bps[2];              // [sub]: bp pairs
    ulonglong2 bg1s[2];             // [sub]: bg1 pairs
    float bg2[TT];
    float dc[TT];
    float bo;
};

__global__ void __launch_bounds__(BLK)
horizon_kernel(const float* __restrict__ x, const float* __restrict__ last_step,
               const float* __restrict__ W_ih, const float* __restrict__ W_hh,
               const float* __restrict__ b_ih, const float* __restrict__ b_hh,
               const float* __restrict__ Wp, const float* __restrict__ bp,
               const float* __restrict__ Wo, const float* __restrict__ bo,
               const float* __restrict__ Wg1, const float* __restrict__ bg1,
               const float* __restrict__ Wg2, const float* __restrict__ bg2,
               const float* __restrict__ log_decay, float* __restrict__ out) {
    __shared__ Smem s;
    const int tid = threadIdx.x;
    const int sub = tid & 1;        // which half of the hidden lanes this thread owns
    const int rl  = tid >> 1;       // local row 0..63
    const int rb  = blockIdx.x * RPB;

    // ---------------- weight prep (packed u64-pair, sub-split layouts) ----------------
    for (int i = tid; i < DD * 4; i += BLK) {
        int d = i >> 2, ss = (i >> 1) & 1, g = i & 1;
        const float* W = (g == 0) ? Wp : Wg1;
        int b = 4 * ss;
        s.wprojs[d][ss][g] = make_ulonglong2(
            pk(W[(b + 0) * DD + d], W[(b + 1) * DD + d]),
            pk(W[(b + 2) * DD + d], W[(b + 3) * DD + d]));
    }
    if (tid < 48) {
        int j = tid / 6, r2 = tid % 6, ss = r2 / 3, g = r2 % 3;
        int b = g * 8 + 4 * ss;   // row base in W_hh [24][8]
        s.whhs[j][ss][g] = make_ulonglong2(
            pk(W_hh[(b + 0) * HH + j], W_hh[(b + 1) * HH + j]),
            pk(W_hh[(b + 2) * HH + j], W_hh[(b + 3) * HH + j]));
    }
    if (tid < 6) {
        int ss = tid / 3, g = tid % 3;
        int b = g * 8 + 4 * ss;
        s.wihs[ss][g] = make_ulonglong2(pk(W_ih[b], W_ih[b + 1]), pk(W_ih[b + 2], W_ih[b + 3]));
    }
    if (tid < 4) {
        int ss = tid >> 1, g = tid & 1;
        int b = g * 8 + 4 * ss;
        s.bsums[ss][g] = make_ulonglong2(pk(b_ih[b] + b_hh[b], b_ih[b + 1] + b_hh[b + 1]),
                                         pk(b_ih[b + 2] + b_hh[b + 2], b_ih[b + 3] + b_hh[b + 3]));
    }
    if (tid < 2) {
        int b = 16 + 4 * tid;
        s.bains[tid] = make_ulonglong2(pk(b_ih[b], b_ih[b + 1]), pk(b_ih[b + 2], b_ih[b + 3]));
        s.bahns[tid] = make_ulonglong2(pk(b_hh[b], b_hh[b + 1]), pk(b_hh[b + 2], b_hh[b + 3]));
        int c = 4 * tid;
        s.wos[tid]  = make_ulonglong2(pk(Wo[c], Wo[c + 1]), pk(Wo[c + 2], Wo[c + 3]));
        s.bps[tid]  = make_ulonglong2(pk(bp[c], bp[c + 1]), pk(bp[c + 2], bp[c + 3]));
        s.bg1s[tid] = make_ulonglong2(pk(bg1[c], bg1[c + 1]), pk(bg1[c + 2], bg1[c + 3]));
    }
    if (tid < 56) {
        int t = tid >> 1, ss = tid & 1;
        int b = t * HH + 4 * ss;
        s.wg2s[t][ss] = make_ulonglong2(pk(Wg2[b], Wg2[b + 1]), pk(Wg2[b + 2], Wg2[b + 3]));
    }
    if (tid < TT) {
        s.bg2[tid] = bg2[tid];
        float edc = __expf(log_decay[0]);
        s.dc[tid] = __expf(-edc * (float)(tid + 1));
    }
    if (tid == 0) s.bo = bo[0];
    __syncthreads();

    // ---------------- projections: 4 of 8 Wp outputs + 4 of 8 Wg1 outputs per thread ----------------
    u64 acc[4];
    { ulonglong2 b = s.bps[sub];  acc[0] = b.x; acc[1] = b.y; }
    { ulonglong2 b = s.bg1s[sub]; acc[2] = b.x; acc[3] = b.y; }

#pragma unroll 1
    for (int c = 0; c < 8; c++) {
        __syncthreads();
#pragma unroll
        for (int k = 0; k < 4; k++) {
            int idx = k * BLK + tid;          // 0..511 float4s (64 rows x 8)
            int r = idx >> 3, q = idx & 7;
            float4 v = ((const float4*)(x + (size_t)(rb + r) * DD + c * 32))[q];
            s.xs[r][q ^ (r & 7)] = v;
        }
        __syncthreads();
#pragma unroll
        for (int q = 0; q < 8; q++) {
            float4 xv = s.xs[rl][q ^ (rl & 7)];
            float xe0 = xv.x, xe1 = xv.y, xe2 = xv.z, xe3 = xv.w;
            int dbase = (c << 5) + (q << 2);
#pragma unroll
            for (int e = 0; e < 4; e++) {
                float xs_e = (e == 0) ? xe0 : (e == 1) ? xe1 : (e == 2) ? xe2 : xe3;
                u64 xd = dup2(xs_e);
                ulonglong2 w0 = s.wprojs[dbase + e][sub][0];
                ulonglong2 w1 = s.wprojs[dbase + e][sub][1];
                acc[0] = ffma2(w0.x, xd, acc[0]);
                acc[1] = ffma2(w0.y, xd, acc[1]);
                acc[2] = ffma2(w1.x, xd, acc[2]);
                acc[3] = ffma2(w1.y, xd, acc[3]);
            }
        }
    }

    u64 hp0 = acc[0], hp1 = acc[1];           // h lanes 4s..4s+3
    u64 g1u0, g1u1;                            // relu(g1pre) lanes 4s..4s+3
    {
        float2 f0 = upk(acc[2]), f1 = upk(acc[3]);
        g1u0 = pk(fmaxf(f0.x, 0.0f), fmaxf(f0.y, 0.0f));
        g1u1 = pk(fmaxf(f1.x, 0.0f), fmaxf(f1.y, 0.0f));
    }

    // ---------------- GRU rollout (2 threads per row, shfl-paired) ----------------
    const float last = last_step[rb + rl];
    float cur = last;
    float* outrow = out + (size_t)(rb + rl) * TT;
    const unsigned FULL = 0xFFFFFFFFu;

#pragma unroll 1
    for (int t = 0; t < TT; t++) {
        // exchange h halves with partner (tid^1, same warp)
        u64 o0 = __shfl_xor_sync(FULL, hp0, 1);
        u64 o1 = __shfl_xor_sync(FULL, hp1, 1);
        float hs[8];
        {
            float2 a0 = upk(hp0), a1 = upk(hp1), b0 = upk(o0), b1 = upk(o1);
            int mo = 4 * sub, po = 4 * (1 - sub);
            hs[mo + 0] = a0.x; hs[mo + 1] = a0.y; hs[mo + 2] = a1.x; hs[mo + 3] = a1.y;
            hs[po + 0] = b0.x; hs[po + 1] = b0.y; hs[po + 2] = b1.x; hs[po + 3] = b1.y;
        }

        // init accumulators with biases + gi (cur * w_ih)
        u64 ar0, ar1, az0, az1, ain0, ain1, ahn0, ahn1;
        {
            ulonglong2 br = s.bsums[sub][0], bz = s.bsums[sub][1];
            ulonglong2 bi = s.bains[sub],   bh = s.bahns[sub];
            u64 curd = dup2(cur);
            ulonglong2 wr = s.wihs[sub][0], wz = s.wihs[sub][1], wn = s.wihs[sub][2];
            ar0 = ffma2(wr.x, curd, br.x);  ar1 = ffma2(wr.y, curd, br.y);
            az0 = ffma2(wz.x, curd, bz.x);  az1 = ffma2(wz.y, curd, bz.y);
            ain0 = ffma2(wn.x, curd, bi.x); ain1 = ffma2(wn.y, curd, bi.y);
            ahn0 = bh.x; ahn1 = bh.y;
        }
        // gh: h @ W_hh^T for this thread's 12 output lanes
#pragma unroll
        for (int j = 0; j < 8; j++) {
            u64 hd = dup2(hs[j]);
            ulonglong2 wrj = s.whhs[j][sub][0];
            ulonglong2 wzj = s.whhs[j][sub][1];
            ulonglong2 wnj = s.whhs[j][sub][2];
            ar0 = ffma2(wrj.x, hd, ar0);  ar1 = ffma2(wrj.y, hd, ar1);
            az0 = ffma2(wzj.x, hd, az0);  az1 = ffma2(wzj.y, hd, az1);
            ahn0 = ffma2(wnj.x, hd, ahn0); ahn1 = ffma2(wnj.y, hd, ahn1);
        }
        // gates
        u64 r0 = sigmoid2u(ar0), r1 = sigmoid2u(ar1);
        u64 z0 = sigmoid2u(az0), z1 = sigmoid2u(az1);
        u64 n0 = tanh2u(ffma2(r0, ahn0, ain0));
        u64 n1 = tanh2u(ffma2(r1, ahn1, ain1));
        // h_new = n + z*(h - n)
        u64 d0 = ffma2(n0, NEG1U, hp0);
        u64 d1 = ffma2(n1, NEG1U, hp1);
        hp0 = ffma2(z0, d0, n0);
        hp1 = ffma2(z1, d1, n1);
        // partial pred = own-half h_new . Wo ;  partial gate-logit = own-half g1 . Wg2[t]
        ulonglong2 wo = s.wos[sub];
        u64 pacc = ffma2(hp1, wo.y, ffma2(hp0, wo.x, 0ULL));
        ulonglong2 wg = s.wg2s[t][sub];
        u64 lacc = ffma2(g1u1, wg.y, ffma2(g1u0, wg.x, 0ULL));
        float2 pf = upk(pacc), lf = upk(lacc);
        float pred_part = pf.x + pf.y;
        float gate_part = lf.x + lf.y;
        // cross-thread reduce both scalars in one packed shuffle
        u64 pp = pk(pred_part, gate_part);
        u64 po2 = __shfl_xor_sync(FULL, pp, 1);
        float2 pof = upk(po2);
        float pred = pred_part + pof.x + s.bo;
        float lg   = gate_part + pof.y + s.bg2[t];
        float gate = frcp(1.0f + fex2(-L2E * lg));
        cur = pred;

        float gd = last * s.dc[t];
        float f = fmaf(gate, pred - gd, gd);  // gate*pred + (1-gate)*gd
        if ((t & 1) == sub) outrow[t] = f;    // pair splits the 28 stores
    }
}

extern "C" void kernel_launch(void* const* d_in, const int* in_sizes, int n_in,
                              void* d_out, int out_size) {
    const float* x         = (const float*)d_in[0];
    const float* last_step = (const float*)d_in[1];
    const float* W_ih      = (const float*)d_in[2];
    const float* W_hh      = (const float*)d_in[3];
    const float* b_ih      = (const float*)d_in[4];
    const float* b_hh      = (const float*)d_in[5];
    const float* Wp        = (const float*)d_in[6];
    const float* bp        = (const float*)d_in[7];
    const float* Wo        = (const float*)d_in[8];
    const float* bo        = (const float*)d_in[9];
    const float* Wg1       = (const float*)d_in[10];
    const float* bg1       = (const float*)d_in[11];
    const float* Wg2       = (const float*)d_in[12];
    const float* bg2       = (const float*)d_in[13];
    const float* log_decay = (const float*)d_in[14];
    float* out = (float*)d_out;

    horizon_kernel<<<ROWS / RPB, BLK>>>(x, last_step, W_ih, W_hh, b_ih, b_hh,
                                        Wp, bp, Wo, bo, Wg1, bg1, Wg2, bg2,
                                        log_decay, out);
}